// round 1
// baseline (speedup 1.0000x reference)
#include <cuda_runtime.h>
#include <cuda_bf16.h>
#include <stdint.h>

// Problem shape (fixed by setup_inputs)
#define DD   512
#define BQ   1024
#define MKEY 60000
#define TOPK 50
#define NCLS 10

// ---------------- device scratch (static, allocation-free) ----------------
__device__ __nv_bfloat16 g_xhi[(size_t)BQ * DD];
__device__ __nv_bfloat16 g_xlo[(size_t)BQ * DD];
__device__ __nv_bfloat16 g_khi[(size_t)MKEY * DD];
__device__ __nv_bfloat16 g_klo[(size_t)MKEY * DD];
__device__ float         g_scores[(size_t)BQ * MKEY];   // 245.8 MB
__device__ int           g_val_is64;

// ---------------- small PTX helpers ----------------
__device__ __forceinline__ uint32_t s2u(const void* p) {
    return (uint32_t)__cvta_generic_to_shared(p);
}
__device__ __forceinline__ void cpa16(uint32_t dst, const void* src, int sz) {
    asm volatile("cp.async.cg.shared.global [%0], [%1], 16, %2;\n"
                 :: "r"(dst), "l"(src), "r"(sz));
}
__device__ __forceinline__ void cp_commit() {
    asm volatile("cp.async.commit_group;\n");
}
template <int N>
__device__ __forceinline__ void cp_wait() {
    asm volatile("cp.async.wait_group %0;\n" :: "n"(N));
}
__device__ __forceinline__ void ldmx4(uint32_t* r, uint32_t a) {
    asm volatile("ldmatrix.sync.aligned.m8n8.x4.shared.b16 {%0,%1,%2,%3}, [%4];\n"
                 : "=r"(r[0]), "=r"(r[1]), "=r"(r[2]), "=r"(r[3]) : "r"(a));
}
__device__ __forceinline__ void mma_bf16(float* c, const uint32_t* a, const uint32_t* b) {
    asm volatile(
        "mma.sync.aligned.m16n8k16.row.col.f32.bf16.bf16.f32 "
        "{%0,%1,%2,%3},{%4,%5,%6,%7},{%8,%9},{%0,%1,%2,%3};\n"
        : "+f"(c[0]), "+f"(c[1]), "+f"(c[2]), "+f"(c[3])
        : "r"(a[0]), "r"(a[1]), "r"(a[2]), "r"(a[3]), "r"(b[0]), "r"(b[1]));
}

// ---------------- normalize + bf16 split ----------------
// which: 0 -> queries (g_xhi/g_xlo), 1 -> keys (g_khi/g_klo)
__global__ void norm_split_kernel(const float* __restrict__ src, int which) {
    const int row = blockIdx.x;
    const int t   = threadIdx.x;               // 128 threads
    const float* r = src + (size_t)row * DD;

    float v[4];
    float ss = 0.f;
#pragma unroll
    for (int j = 0; j < 4; j++) {
        v[j] = r[t + 128 * j];
        ss += v[j] * v[j];
    }
#pragma unroll
    for (int o = 16; o; o >>= 1) ss += __shfl_xor_sync(0xffffffffu, ss, o);
    __shared__ float ws[4];
    if ((t & 31) == 0) ws[t >> 5] = ss;
    __syncthreads();
    const float tot = ws[0] + ws[1] + ws[2] + ws[3];
    const float inv = 1.0f / fmaxf(sqrtf(tot), 1e-12f);

    __nv_bfloat16* hi = which ? g_khi : g_xhi;
    __nv_bfloat16* lo = which ? g_klo : g_xlo;
#pragma unroll
    for (int j = 0; j < 4; j++) {
        float xn = v[j] * inv;
        __nv_bfloat16 h = __float2bfloat16(xn);
        float rem = xn - __bfloat162float(h);
        size_t o2 = (size_t)row * DD + t + 128 * j;
        hi[o2] = h;
        lo[o2] = __float2bfloat16(rem);
    }
}

// ---------------- values dtype sniffing (jax may demote int64 -> int32) ----------------
__global__ void detect_values_kernel(const void* vals) {
    // Interpret first 64 entries as int64: if all in [0, NCLS) -> true int64.
    // int32 data misread as int64 puts a random 0..9 in the high word -> huge/neg.
    const long long* p = (const long long*)vals;
    int ok = 1;
    for (int i = 0; i < 64; i++) {
        long long vv = p[i];
        if (vv < 0 || vv >= NCLS) { ok = 0; break; }
    }
    g_val_is64 = ok;
}

// ---------------- GEMM: scores = xhi*klo + xlo*khi + xhi*khi (K = 3*512) ----------------
// CTA tile 128(queries) x 128(keys), KT=32, 256 threads = 8 warps (2x4),
// warp tile 64x32 via 4x4 m16n8k16 mma.
#define KT   32
#define PAD  40      // halves per smem row (32 data + 8 pad) -> 80B stride, ldmatrix conflict-free
#define NT_TILES 48  // 1536 / 32

__global__ void __launch_bounds__(256) gemm3_kernel(int M) {
    __shared__ alignas(16) __nv_bfloat16 As[2][128 * PAD];
    __shared__ alignas(16) __nv_bfloat16 Bs[2][128 * PAD];

    const int tid  = threadIdx.x;
    const int lane = tid & 31;
    const int w    = tid >> 5;
    const int wm   = w & 1;        // 0..1  -> 64-row slab
    const int wn   = w >> 1;       // 0..3  -> 32-col slab
    const int bm0  = blockIdx.x * 128;
    const int bn0  = blockIdx.y * 128;

    float acc[4][4][4];
#pragma unroll
    for (int a = 0; a < 4; a++)
#pragma unroll
        for (int b = 0; b < 4; b++)
#pragma unroll
            for (int c = 0; c < 4; c++) acc[a][b][c] = 0.f;

    auto load_tile = [&](int t, int buf) {
        const int kk0  = t * KT;
        const int seg  = kk0 >> 9;        // 0: xhi*klo, 1: xlo*khi, 2: xhi*khi
        const int koff = kk0 & 511;
        const __nv_bfloat16* Asrc = (seg == 1) ? g_xlo : g_xhi;
        const __nv_bfloat16* Bsrc = (seg == 0) ? g_klo : g_khi;
#pragma unroll
        for (int i = 0; i < 2; i++) {
            const int c   = tid + i * 256;     // 512 16B-chunks per tile
            const int r   = c >> 2;            // 4 chunks per row
            const int sub = c & 3;
            // A (always in range: bm0+r < 1024)
            cpa16(s2u(&As[buf][r * PAD + sub * 8]),
                  Asrc + (size_t)(bm0 + r) * DD + koff + sub * 8, 16);
            // B (guard key row)
            const int gr = bn0 + r;
            const int ok = (gr < M) ? 16 : 0;
            const int grc = (gr < M) ? gr : (M - 1);
            cpa16(s2u(&Bs[buf][r * PAD + sub * 8]),
                  Bsrc + (size_t)grc * DD + koff + sub * 8, ok);
        }
    };

    load_tile(0, 0);
    cp_commit();

    for (int t = 0; t < NT_TILES; t++) {
        const int buf = t & 1;
        if (t + 1 < NT_TILES) load_tile(t + 1, buf ^ 1);
        cp_commit();
        cp_wait<1>();
        __syncthreads();

#pragma unroll
        for (int kh = 0; kh < 2; kh++) {
            uint32_t afr[4][4];
#pragma unroll
            for (int mt = 0; mt < 4; mt++) {
                const int r = wm * 64 + mt * 16 + (lane & 15);
                const int c = kh * 16 + ((lane >> 4) << 3);
                ldmx4(afr[mt], s2u(&As[buf][r * PAD + c]));
            }
            uint32_t bfr[4][2];
#pragma unroll
            for (int np = 0; np < 2; np++) {
                const int q  = lane >> 3;
                const int rr = wn * 32 + np * 16 + ((q >> 1) << 3) + (lane & 7);
                const int cc = kh * 16 + ((q & 1) << 3);
                uint32_t tmp[4];
                ldmx4(tmp, s2u(&Bs[buf][rr * PAD + cc]));
                bfr[np * 2 + 0][0] = tmp[0];
                bfr[np * 2 + 0][1] = tmp[1];
                bfr[np * 2 + 1][0] = tmp[2];
                bfr[np * 2 + 1][1] = tmp[3];
            }
#pragma unroll
            for (int mt = 0; mt < 4; mt++)
#pragma unroll
                for (int nt = 0; nt < 4; nt++)
                    mma_bf16(acc[mt][nt], afr[mt], bfr[nt]);
        }
        __syncthreads();
    }

    // epilogue -> fp32 scores
#pragma unroll
    for (int mt = 0; mt < 4; mt++) {
#pragma unroll
        for (int nt = 0; nt < 4; nt++) {
            const int r0 = bm0 + wm * 64 + mt * 16 + (lane >> 2);
            const int c0 = bn0 + wn * 32 + nt * 8 + (lane & 3) * 2;
            if (c0 < M)     g_scores[(size_t)r0 * M + c0]           = acc[mt][nt][0];
            if (c0 + 1 < M) g_scores[(size_t)r0 * M + c0 + 1]       = acc[mt][nt][1];
            if (c0 < M)     g_scores[(size_t)(r0 + 8) * M + c0]     = acc[mt][nt][2];
            if (c0 + 1 < M) g_scores[(size_t)(r0 + 8) * M + c0 + 1] = acc[mt][nt][3];
        }
    }
}

// ---------------- per-row top-k + class vote ----------------
__device__ __forceinline__ unsigned mono_u32(float v) {
    unsigned u = __float_as_uint(v);
    return (u & 0x80000000u) ? ~u : (u | 0x80000000u);
}

__global__ void __launch_bounds__(256) topk_vote_kernel(
    const void* __restrict__ values_raw, float* __restrict__ out, int M) {
    const int b    = blockIdx.x;
    const int tid  = threadIdx.x;
    const int lane = tid & 31;
    const int w    = tid >> 5;

    __shared__ unsigned hist[4096];
    __shared__ unsigned chs[256];
    __shared__ int      sT;
    __shared__ unsigned sNc;
    __shared__ unsigned cand_u[2048];
    __shared__ int      cand_i[2048];
    __shared__ float    cand_v[2048];
    __shared__ unsigned long long redK[8];
    __shared__ int      redS[8];
    __shared__ float    cls[NCLS];

    for (int i = tid; i < 4096; i += 256) hist[i] = 0u;
    if (tid < NCLS) cls[tid] = 0.f;
    if (tid == 0) sNc = 0u;
    __syncthreads();

    const float* row = g_scores + (size_t)b * M;

    // pass 1: 12-bit radix histogram over monotone float bits
    for (int i = tid; i < M; i += 256) {
        atomicAdd(&hist[mono_u32(row[i]) >> 20], 1u);
    }
    __syncthreads();

    unsigned s = 0;
#pragma unroll
    for (int j = 0; j < 16; j++) s += hist[tid * 16 + j];
    chs[tid] = s;
    __syncthreads();

    if (tid == 0) {
        unsigned cum = 0;
        int c = 255;
        for (; c >= 0; c--) {
            if (cum + chs[c] >= TOPK) break;
            cum += chs[c];
        }
        int T = c * 16;
        for (int d = c * 16 + 15; d >= c * 16; d--) {
            if (cum + hist[d] >= TOPK) { T = d; break; }
            cum += hist[d];
        }
        sT = T;
    }
    __syncthreads();
    const int T = sT;

    // pass 2: collect candidates (digit >= T): ~50-100 expected
    for (int i = tid; i < M; i += 256) {
        float v = row[i];
        unsigned u = mono_u32(v);
        if ((int)(u >> 20) >= T) {
            unsigned p = atomicAdd(&sNc, 1u);
            if (p < 2048u) { cand_u[p] = u; cand_i[p] = i; cand_v[p] = v; }
        }
    }
    __syncthreads();
    const int n = (int)min(sNc, 2048u);
    const int is64 = g_val_is64;
    const long long* v64 = (const long long*)values_raw;
    const int*       v32 = (const int*)values_raw;

    // exact top-50 (tie-break: score desc, index asc — matches lax.top_k)
    for (int it = 0; it < TOPK; it++) {
        unsigned long long best = 0ull;
        int bslot = -1;
        for (int j = tid; j < n; j += 256) {
            unsigned long long key =
                ((unsigned long long)cand_u[j] << 32) |
                (unsigned long long)(0xFFFFFFFFu - (unsigned)cand_i[j]);
            if (key > best) { best = key; bslot = j; }
        }
#pragma unroll
        for (int o = 16; o; o >>= 1) {
            unsigned long long ok = __shfl_xor_sync(0xffffffffu, best, o);
            int os = __shfl_xor_sync(0xffffffffu, bslot, o);
            if (ok > best) { best = ok; bslot = os; }
        }
        if (lane == 0) { redK[w] = best; redS[w] = bslot; }
        __syncthreads();
        if (tid == 0) {
            unsigned long long bb = 0ull;
            int ss2 = -1;
            for (int q = 0; q < 8; q++)
                if (redK[q] > bb) { bb = redK[q]; ss2 = redS[q]; }
            if (ss2 >= 0) {
                int idx = cand_i[ss2];
                int lbl = is64 ? (int)v64[idx] : v32[idx];
                if (lbl >= 0 && lbl < NCLS) cls[lbl] += cand_v[ss2];
                cand_u[ss2] = 0u;   // remove from further consideration
            }
        }
        __syncthreads();
    }

    if (tid < NCLS) out[b * NCLS + tid] = cls[tid];
}

// ---------------- launcher ----------------
extern "C" void kernel_launch(void* const* d_in, const int* in_sizes, int n_in,
                              void* d_out, int out_size) {
    const float* x      = (const float*)d_in[0];
    const float* keys   = (const float*)d_in[1];
    const void*  values = d_in[2];
    float*       out    = (float*)d_out;

    const int B = in_sizes[0] / DD;   // 1024
    const int M = in_sizes[2];        // 60000

    norm_split_kernel<<<B, 128>>>(x, 0);
    norm_split_kernel<<<M, 128>>>(keys, 1);
    detect_values_kernel<<<1, 1>>>(values);

    dim3 grid(B / 128, (M + 127) / 128);
    gemm3_kernel<<<grid, 256>>>(M);

    topk_vote_kernel<<<B, 256>>>(values, out, M);
}